// round 5
// baseline (speedup 1.0000x reference)
#include <cuda_runtime.h>
#include <math.h>

#define SEQ 512
#define BATCH 256
#define HID 256
#define H3 768

// ---------------- device globals (no cudaMalloc allowed) ----------------
// Packed layer-1 weights: B1[k][c], k in [0,512), c = j*4+g, g in {r, z, n_ih, n_hh}
//   k<256 -> input (x) part uses Wih1, k>=256 -> hidden part uses Whh1.
//   g==2 (n_ih) zero for k>=256; g==3 (n_hh) zero for k<256.
__device__ float g_B1[512 * 1024];
// gh2 weights transposed: Bgh2[k][n] = qWhh2[n][k]
__device__ float g_Bgh2[256 * 768];
// Packed layer-2 input weights: B2[k][c], c = j*3+g, g in {r,z,n}: qWih2[j+g*256][k]
__device__ float g_B2[256 * 768];

__device__ float g_h1[2][BATCH * HID];
__device__ float g_h2[2][BATCH * HID];
__device__ float g_gh2[BATCH * H3];
__device__ float g_scale[4];
__device__ unsigned g_bar;

// ---------------- init: zero barrier, load initial hidden state ----------------
__global__ void k_init(const float* __restrict__ h1, const float* __restrict__ h2) {
    int i = blockIdx.x * blockDim.x + threadIdx.x;
    if (i == 0) g_bar = 0u;
    if (i < BATCH * HID) {
        g_h1[0][i] = h1[i];
        g_h2[0][i] = h2[i];
    }
}

// ---------------- per-tensor max-abs -> scale ----------------
__global__ void k_scales(const float* __restrict__ w0, const float* __restrict__ w1,
                         const float* __restrict__ w2, const float* __restrict__ w3) {
    const float* w = (blockIdx.x == 0) ? w0 : (blockIdx.x == 1) ? w1
                   : (blockIdx.x == 2) ? w2 : w3;
    const int n = H3 * 256;
    float m = 0.f;
    for (int i = threadIdx.x; i < n; i += blockDim.x) m = fmaxf(m, fabsf(w[i]));
    __shared__ float sm[512];
    sm[threadIdx.x] = m;
    __syncthreads();
    for (int s = blockDim.x >> 1; s > 0; s >>= 1) {
        if (threadIdx.x < s) sm[threadIdx.x] = fmaxf(sm[threadIdx.x], sm[threadIdx.x + s]);
        __syncthreads();
    }
    if (threadIdx.x == 0) g_scale[blockIdx.x] = sm[0] / 127.0f;
}

__device__ __forceinline__ float quantize(float v, float s) {
    return rintf(v / s) * s;  // round-half-even, matches jnp.round
}

// ---------------- build packed / quantized weight matrices ----------------
__global__ void k_pack(const float* __restrict__ wih1, const float* __restrict__ whh1,
                       const float* __restrict__ wih2, const float* __restrict__ whh2) {
    const float s0 = g_scale[0], s1 = g_scale[1], s2 = g_scale[2], s3 = g_scale[3];
    const int N1 = 512 * 1024;
    const int N2 = 256 * 768;
    const int NT = N1 + 2 * N2;
    for (int idx = blockIdx.x * blockDim.x + threadIdx.x; idx < NT;
         idx += gridDim.x * blockDim.x) {
        if (idx < N1) {
            int k = idx >> 10, c = idx & 1023;
            int j = c >> 2, g = c & 3;
            float out = 0.f;
            if (g == 0 || g == 1) {
                int row = j + (g == 1 ? 256 : 0);
                if (k < 256) out = quantize(wih1[row * 256 + k], s0);
                else         out = quantize(whh1[row * 256 + (k - 256)], s1);
            } else if (g == 2) {
                if (k < 256) out = quantize(wih1[(j + 512) * 256 + k], s0);
            } else {
                if (k >= 256) out = quantize(whh1[(j + 512) * 256 + (k - 256)], s1);
            }
            g_B1[idx] = out;
        } else if (idx < N1 + N2) {
            int r = idx - N1;
            int k = r / 768, n = r % 768;
            g_Bgh2[r] = quantize(whh2[n * 256 + k], s3);
        } else {
            int r = idx - N1 - N2;
            int k = r / 768, c = r % 768;
            int j = c / 3, g = c % 3;
            g_B2[r] = quantize(wih2[(j + g * 256) * 256 + k], s2);
        }
    }
}

// ---------------- grid barrier: monotonic ticket counter ----------------
__device__ __forceinline__ void grid_sync(unsigned G) {
    __syncthreads();
    if (threadIdx.x == 0) {
        __threadfence();
        unsigned t = atomicAdd(&g_bar, 1u) + 1u;
        unsigned target = ((t + G - 1u) / G) * G;
        while (*(volatile unsigned*)&g_bar < target) { }
        __threadfence();
    }
    __syncthreads();
}

__device__ __forceinline__ float sigf(float x) { return 1.f / (1.f + expf(-x)); }

// ---------------- main persistent kernel ----------------
// 256 threads/block. thread -> (cx = tid&15 : j-lane, by = tid>>4 : row pair)
__global__ void __launch_bounds__(256, 2) k_main(
    const float* __restrict__ x,
    const float* __restrict__ b_ih1, const float* __restrict__ b_hh1,
    const float* __restrict__ b_ih2, const float* __restrict__ b_hh2,
    float* __restrict__ out, int G)
{
    __shared__ float sA[32 * 36];   // 32 rows, stride 36 (pad, 16B-aligned rows)
    __shared__ float sB[32 * 64];   // up to 32 x 64

    const int tid = threadIdx.x;
    const int bid = blockIdx.x;
    const int cx = tid & 15;
    const int by = tid >> 4;

    for (int t = 0; t < SEQ; ++t) {
        const int cur = t & 1, nxt = cur ^ 1;
        const float* xt  = x + (size_t)t * BATCH * 256;
        const float* h1c = g_h1[cur];
        float*       h1n = g_h1[nxt];
        const float* h2c = g_h2[cur];
        float*       h2n = g_h2[nxt];

        // =================== Phase A ===================
        // tasks 0..127   : fused layer-1 tiles  (BM=32 x 16 j's, K=512)
        // tasks 128..255 : gh2 tiles            (BM=32 x 48 n's, K=256)
        for (int task = bid; task < 256; task += G) {
            if (task < 128) {
                const int bt = task >> 4, jt = task & 15;
                const int b0 = bt * 32, j0 = jt * 16, c0 = jt * 64;
                float acc[2][4] = {};
                for (int k0 = 0; k0 < 512; k0 += 32) {
                    {   // A chunk: 32x32 from x (k<256) or h1 (k>=256)
                        int v = tid, r = v >> 3, k4 = (v & 7) << 2;
                        const float* src = (k0 < 256)
                            ? (xt  + (b0 + r) * 256 + k0 + k4)
                            : (h1c + (b0 + r) * 256 + (k0 - 256) + k4);
                        float4 av = *(const float4*)src;
                        *(float4*)&sA[r * 36 + k4] = av;
                    }
                    {   // B chunk: 32 x 64 from g_B1
                        #pragma unroll
                        for (int v = tid; v < 512; v += 256) {
                            int r = v >> 4, c4 = (v & 15) << 2;
                            *(float4*)&sB[r * 64 + c4] =
                                *(const float4*)&g_B1[(size_t)(k0 + r) * 1024 + c0 + c4];
                        }
                    }
                    __syncthreads();
                    #pragma unroll
                    for (int kk = 0; kk < 32; ++kk) {
                        float a0 = sA[(by * 2 + 0) * 36 + kk];
                        float a1 = sA[(by * 2 + 1) * 36 + kk];
                        float4 bv = *(const float4*)&sB[kk * 64 + cx * 4];
                        acc[0][0] += a0 * bv.x; acc[0][1] += a0 * bv.y;
                        acc[0][2] += a0 * bv.z; acc[0][3] += a0 * bv.w;
                        acc[1][0] += a1 * bv.x; acc[1][1] += a1 * bv.y;
                        acc[1][2] += a1 * bv.z; acc[1][3] += a1 * bv.w;
                    }
                    __syncthreads();
                }
                // gates epilogue -> h1_new
                const int j = j0 + cx;
                const float br  = b_ih1[j]       + b_hh1[j];
                const float bz  = b_ih1[j + 256] + b_hh1[j + 256];
                const float bni = b_ih1[j + 512];
                const float bnh = b_hh1[j + 512];
                #pragma unroll
                for (int r = 0; r < 2; ++r) {
                    int b = b0 + by * 2 + r;
                    float rg = sigf(acc[r][0] + br);
                    float zg = sigf(acc[r][1] + bz);
                    float ng = tanhf(acc[r][2] + bni + rg * (acc[r][3] + bnh));
                    float ho = h1c[b * 256 + j];
                    h1n[b * 256 + j] = (1.f - zg) * ng + zg * ho;
                }
            } else {
                // gh2 = h2 @ Whh2^T  (plain tile, BM=32 x BN=48, K=256)
                const int idx = task - 128;
                const int bt = idx >> 4, nt = idx & 15;
                const int b0 = bt * 32, n0 = nt * 48;
                float acc[2][3] = {};
                for (int k0 = 0; k0 < 256; k0 += 32) {
                    {   int v = tid, r = v >> 3, k4 = (v & 7) << 2;
                        *(float4*)&sA[r * 36 + k4] =
                            *(const float4*)(h2c + (b0 + r) * 256 + k0 + k4);
                    }
                    {   // 32 x 48 = 384 float4
                        for (int v = tid; v < 384; v += 256) {
                            int r = v / 12, c4 = (v % 12) << 2;
                            *(float4*)&sB[r * 48 + c4] =
                                *(const float4*)&g_Bgh2[(k0 + r) * 768 + n0 + c4];
                        }
                    }
                    __syncthreads();
                    #pragma unroll
                    for (int kk = 0; kk < 32; ++kk) {
                        float a0 = sA[(by * 2 + 0) * 36 + kk];
                        float a1 = sA[(by * 2 + 1) * 36 + kk];
                        float w0 = sB[kk * 48 + cx * 3 + 0];
                        float w1 = sB[kk * 48 + cx * 3 + 1];
                        float w2 = sB[kk * 48 + cx * 3 + 2];
                        acc[0][0] += a0 * w0; acc[0][1] += a0 * w1; acc[0][2] += a0 * w2;
                        acc[1][0] += a1 * w0; acc[1][1] += a1 * w1; acc[1][2] += a1 * w2;
                    }
                    __syncthreads();
                }
                #pragma unroll
                for (int r = 0; r < 2; ++r) {
                    int b = b0 + by * 2 + r;
                    g_gh2[b * 768 + n0 + cx * 3 + 0] = acc[r][0];
                    g_gh2[b * 768 + n0 + cx * 3 + 1] = acc[r][1];
                    g_gh2[b * 768 + n0 + cx * 3 + 2] = acc[r][2];
                }
            }
        }
        grid_sync((unsigned)G);

        // =================== Phase B ===================
        // tasks 0..127 : fused layer-2 tiles (BM=32 x 16 j's, K=256, 3 groups)
        for (int task = bid; task < 128; task += G) {
            const int bt = task >> 4, jt = task & 15;
            const int b0 = bt * 32, j0 = jt * 16, c0 = jt * 48;
            float acc[2][3] = {};
            for (int k0 = 0; k0 < 256; k0 += 32) {
                {   int v = tid, r = v >> 3, k4 = (v & 7) << 2;
                    *(float4*)&sA[r * 36 + k4] =
                        *(const float4*)(h1n + (b0 + r) * 256 + k0 + k4);
                }
                {   for (int v = tid; v < 384; v += 256) {
                        int r = v / 12, c4 = (v % 12) << 2;
                        *(float4*)&sB[r * 48 + c4] =
                            *(const float4*)&g_B2[(k0 + r) * 768 + c0 + c4];
                    }
                }
                __syncthreads();
                #pragma unroll
                for (int kk = 0; kk < 32; ++kk) {
                    float a0 = sA[(by * 2 + 0) * 36 + kk];
                    float a1 = sA[(by * 2 + 1) * 36 + kk];
                    float w0 = sB[kk * 48 + cx * 3 + 0];
                    float w1 = sB[kk * 48 + cx * 3 + 1];
                    float w2 = sB[kk * 48 + cx * 3 + 2];
                    acc[0][0] += a0 * w0; acc[0][1] += a0 * w1; acc[0][2] += a0 * w2;
                    acc[1][0] += a1 * w0; acc[1][1] += a1 * w1; acc[1][2] += a1 * w2;
                }
                __syncthreads();
            }
            const int j = j0 + cx;
            const float bi_r = b_ih2[j],       bh_r = b_hh2[j];
            const float bi_z = b_ih2[j + 256], bh_z = b_hh2[j + 256];
            const float bi_n = b_ih2[j + 512], bh_n = b_hh2[j + 512];
            #pragma unroll
            for (int r = 0; r < 2; ++r) {
                int b = b0 + by * 2 + r;
                float hr = g_gh2[b * 768 + j]       + bh_r;
                float hz = g_gh2[b * 768 + j + 256] + bh_z;
                float hn = g_gh2[b * 768 + j + 512] + bh_n;
                float rg = sigf(acc[r][0] + bi_r + hr);
                float zg = sigf(acc[r][1] + bi_z + hz);
                float ng = tanhf(acc[r][2] + bi_n + rg * hn);
                float ho = h2c[b * 256 + j];
                h2n[b * 256 + j] = (1.f - zg) * ng + zg * ho;
            }
        }
        grid_sync((unsigned)G);
    }

    // final h2 lives in g_h2[0] (SEQ=512 even: last nxt == 0)
    for (int i = bid * 256 + tid; i < BATCH * HID; i += G * 256)
        out[i] = g_h2[0][i];
}

// ---------------- host launch ----------------
extern "C" void kernel_launch(void* const* d_in, const int* in_sizes, int n_in,
                              void* d_out, int out_size) {
    (void)in_sizes; (void)n_in; (void)out_size;
    const float* x     = (const float*)d_in[0];
    const float* h1    = (const float*)d_in[1];
    const float* h2    = (const float*)d_in[2];
    const float* w_ih1 = (const float*)d_in[3];
    const float* w_hh1 = (const float*)d_in[4];
    const float* b_ih1 = (const float*)d_in[5];
    const float* b_hh1 = (const float*)d_in[6];
    const float* w_ih2 = (const float*)d_in[7];
    const float* w_hh2 = (const float*)d_in[8];
    const float* b_ih2 = (const float*)d_in[9];
    const float* b_hh2 = (const float*)d_in[10];
    float* out = (float*)d_out;

    int dev = 0;
    cudaGetDevice(&dev);
    int numSM = 148;
    cudaDeviceGetAttribute(&numSM, cudaDevAttrMultiProcessorCount, dev);
    int occ = 1;
    cudaOccupancyMaxActiveBlocksPerMultiprocessor(&occ, k_main, 256, 0);
    if (occ < 1) occ = 1;
    if (occ > 2) occ = 2;
    int G = numSM * occ;

    k_init<<<256, 256>>>(h1, h2);
    k_scales<<<4, 512>>>(w_ih1, w_hh1, w_ih2, w_hh2);
    k_pack<<<1024, 256>>>(w_ih1, w_hh1, w_ih2, w_hh2);
    k_main<<<G, 256>>>(x, b_ih1, b_hh1, b_ih2, b_hh2, out, G);
}

// round 6
// speedup vs baseline: 1.8428x; 1.8428x over previous
#include <cuda_runtime.h>
#include <math.h>

typedef unsigned long long ull;

#define SEQ 512

// ---------------- device globals (no cudaMalloc allowed) ----------------
// packed quantized weights: [k][j*3+g], g in {r,z,n}; 256x768 each
__device__ float gW1x[256 * 768];   // layer1 input half  (from w_ih1)
__device__ float gW1h[256 * 768];   // layer1 hidden half (from w_hh1)
__device__ float gW2i[256 * 768];   // layer2 input half  (from w_ih2)
__device__ float gW2h[256 * 768];   // layer2 hidden half (from w_hh2)

// transposed hidden states: [j][b], double-buffered by phase parity
__device__ float g_h1T[2][256 * 256];
__device__ float g_h2T[2][256 * 256];
// transposed input: [t][k][b]  (134 MB scratch)
__device__ float g_xT[SEQ * 256 * 256];

__device__ float g_scale[4];
__device__ unsigned g_bar;

// ---------------- init: reset barrier, load transposed initial state ----------------
__global__ void k_init(const float* __restrict__ h1, const float* __restrict__ h2) {
    int i = blockIdx.x * blockDim.x + threadIdx.x;
    if (i == 0) g_bar = 0u;
    if (i < 256 * 256) {
        int j = i >> 8, b = i & 255;
        g_h1T[0][i] = h1[b * 256 + j];   // read at phase 0 (par=0)
        g_h2T[1][i] = h2[b * 256 + j];   // read at phase 1 (par=1)
    }
}

// ---------------- per-tensor max-abs -> scale ----------------
__global__ void k_scales(const float* __restrict__ w0, const float* __restrict__ w1,
                         const float* __restrict__ w2, const float* __restrict__ w3) {
    const float* w = (blockIdx.x == 0) ? w0 : (blockIdx.x == 1) ? w1
                   : (blockIdx.x == 2) ? w2 : w3;
    const int n = 768 * 256;
    float m = 0.f;
    for (int i = threadIdx.x; i < n; i += blockDim.x) m = fmaxf(m, fabsf(w[i]));
    __shared__ float sm[512];
    sm[threadIdx.x] = m;
    __syncthreads();
    for (int s = blockDim.x >> 1; s > 0; s >>= 1) {
        if (threadIdx.x < s) sm[threadIdx.x] = fmaxf(sm[threadIdx.x], sm[threadIdx.x + s]);
        __syncthreads();
    }
    if (threadIdx.x == 0) g_scale[blockIdx.x] = sm[0] / 127.0f;
}

__device__ __forceinline__ float quantize(float v, float s) {
    return rintf(v / s) * s;  // round-half-even, matches jnp.round
}

// ---------------- build packed quantized weights [k][j*3+g] ----------------
__global__ void k_pack(const float* __restrict__ wih1, const float* __restrict__ whh1,
                       const float* __restrict__ wih2, const float* __restrict__ whh2) {
    const float s0 = g_scale[0], s1 = g_scale[1], s2 = g_scale[2], s3 = g_scale[3];
    const int N = 256 * 768;
    for (int i = blockIdx.x * blockDim.x + threadIdx.x; i < N;
         i += gridDim.x * blockDim.x) {
        int k = i / 768, c = i - k * 768;
        int j = c / 3, g = c - j * 3;
        int off = (j + g * 256) * 256 + k;
        gW1x[i] = quantize(wih1[off], s0);
        gW1h[i] = quantize(whh1[off], s1);
        gW2i[i] = quantize(wih2[off], s2);
        gW2h[i] = quantize(whh2[off], s3);
    }
}

// ---------------- one-time x transpose: x[t][b][k] -> g_xT[t][k][b] ----------------
__global__ void k_transx(const float* __restrict__ x) {
    __shared__ float tile[32][33];
    const int t = blockIdx.z;
    const int bi = blockIdx.x * 32, ki = blockIdx.y * 32;
    const int tx = threadIdx.x & 31, ty = threadIdx.x >> 5;  // 32 x 8
    const float* xs = x + (size_t)t * 65536;
    float* xd = g_xT + (size_t)t * 65536;
    #pragma unroll
    for (int r = 0; r < 4; ++r) {
        int bl = ty + r * 8;
        tile[bl][tx] = xs[(bi + bl) * 256 + ki + tx];
    }
    __syncthreads();
    #pragma unroll
    for (int r = 0; r < 4; ++r) {
        int kl = ty + r * 8;
        xd[(ki + kl) * 256 + bi + tx] = tile[tx][kl];
    }
}

// ---------------- grid barrier: monotonic ticket counter (G=128) ----------------
__device__ __forceinline__ void grid_sync() {
    __syncthreads();
    if (threadIdx.x == 0) {
        __threadfence();
        unsigned t = atomicAdd(&g_bar, 1u) + 1u;
        unsigned target = ((t + 127u) / 128u) * 128u;
        while (*(volatile unsigned*)&g_bar < target) { }
        __threadfence();
    }
    __syncthreads();
}

__device__ __forceinline__ float sigf(float x) { return 1.f / (1.f + expf(-x)); }

__device__ __forceinline__ ull f2fma(ull a, ull b, ull c) {
    ull d;
    asm("fma.rn.f32x2 %0, %1, %2, %3;" : "=l"(d) : "l"(a), "l"(b), "l"(c));
    return d;
}

union UF { ull u; float2 f; };
__device__ __forceinline__ void unpk(const ull* a, float* o) {
    UF t0, t1; t0.u = a[0]; t1.u = a[1];
    o[0] = t0.f.x; o[1] = t0.f.y; o[2] = t1.f.x; o[3] = t1.f.y;
}

// ---------------- K=256 half-GEMM: 3 gate accumulators, f32x2 math ----------------
// src: transposed activations [256 k][256 b]; sW rows [kbase, kbase+256)
// thread: cx = j lane (16), by = row group (16), 4 rows packed as 2 f32x2
__device__ __forceinline__ void gemm_half(
    const float* __restrict__ src, int kbase, int b0,
    float* __restrict__ sA, const float2* __restrict__ sW,
    int cx, int by, int tid, ull* g0, ull* g1, ull* g2)
{
    const int lk = tid >> 4;           // 0..15
    const int lc = (tid & 15) << 2;    // 0..60
    const float* s = src + b0 + lc;
    float4 p0 = *(const float4*)(s + (size_t)lk * 256);
    float4 p1 = *(const float4*)(s + (size_t)(lk + 16) * 256);
    for (int ch = 0; ch < 8; ++ch) {
        float* buf = sA + (ch & 1) * (32 * 64);
        *(float4*)(buf + lk * 64 + lc) = p0;
        *(float4*)(buf + (lk + 16) * 64 + lc) = p1;
        __syncthreads();
        if (ch < 7) {
            p0 = *(const float4*)(s + (size_t)((ch + 1) * 32 + lk) * 256);
            p1 = *(const float4*)(s + (size_t)((ch + 1) * 32 + lk + 16) * 256);
        }
        const float2* w = sW + (size_t)(kbase + ch * 32) * 48 + cx * 3;
        const float* ab = buf + by * 4;
        #pragma unroll
        for (int kk = 0; kk < 32; ++kk) {
            float4 av = *(const float4*)(ab + kk * 64);
            ull a01 = ((const ull*)&av)[0];
            ull a23 = ((const ull*)&av)[1];
            ull w0 = *(const ull*)(w + (size_t)kk * 48);
            ull w1 = *(const ull*)(w + (size_t)kk * 48 + 1);
            ull w2 = *(const ull*)(w + (size_t)kk * 48 + 2);
            g0[0] = f2fma(a01, w0, g0[0]);
            g0[1] = f2fma(a23, w0, g0[1]);
            g1[0] = f2fma(a01, w1, g1[0]);
            g1[1] = f2fma(a23, w1, g1[1]);
            g2[0] = f2fma(a01, w2, g2[0]);
            g2[1] = f2fma(a23, w2, g2[1]);
        }
    }
}

// ---------------- main persistent kernel: G=128 blocks x 256 threads ----------------
// blocks 0..63  : layer-1 tasks (BM=64 rows x 16 j), active phases 0..511
// blocks 64..127: layer-2 tasks (same shape),        active phases 1..512
__global__ void __launch_bounds__(256) k_main(
    const float* __restrict__ b_ih1, const float* __restrict__ b_hh1,
    const float* __restrict__ b_ih2, const float* __restrict__ b_hh2,
    float* __restrict__ out)
{
    extern __shared__ float2 dsm[];
    float2* sW = dsm;                          // [512][48] duplicated pairs (196.6 KB)
    float* sA = (float*)(dsm + 512 * 48);      // [2][32][64] activations (16 KB)

    const int tid = threadIdx.x, bid = blockIdx.x;
    const int cx = tid & 15, by = tid >> 4;
    const bool isL2 = bid >= 64;
    const int tb = isL2 ? bid - 64 : bid;
    const int rb = tb >> 4, jb = tb & 15;
    const int b0 = rb * 64;
    const int j0 = jb * 16;
    const int j = j0 + cx;

    // load this block's weight tile into SMEM once (duplicated (w,w) pairs)
    {
        const float* Wa = isL2 ? gW2i : gW1x;
        const float* Wb = isL2 ? gW2h : gW1h;
        for (int i = tid; i < 512 * 48; i += 256) {
            int kk = i / 48, c = i - kk * 48;
            float wv = (kk < 256) ? Wa[kk * 768 + j0 * 3 + c]
                                  : Wb[(kk - 256) * 768 + j0 * 3 + c];
            sW[(size_t)kk * 48 + c] = make_float2(wv, wv);
        }
    }
    // per-thread biases (j fixed for whole kernel)
    float bR, bZ, bNi, bNh;
    if (!isL2) {
        bR  = b_ih1[j] + b_hh1[j];
        bZ  = b_ih1[j + 256] + b_hh1[j + 256];
        bNi = b_ih1[j + 512];
        bNh = b_hh1[j + 512];
    } else {
        bR  = b_ih2[j] + b_hh2[j];
        bZ  = b_ih2[j + 256] + b_hh2[j + 256];
        bNi = b_ih2[j + 512];
        bNh = b_hh2[j + 512];
    }
    __syncthreads();

    const int hoff = j * 256 + b0 + by * 4;

    for (int p = 0; p <= SEQ; ++p) {
        const int par = p & 1;
        if (!isL2) {
            if (p < SEQ) {
                // layer1: h1(p+1) = GRU(x[p], h1(p))
                ull aR[2] = {0, 0}, aZ[2] = {0, 0}, aNi[2] = {0, 0}, aNh[2] = {0, 0};
                gemm_half(g_xT + (size_t)p * 65536, 0,   b0, sA, sW, cx, by, tid, aR, aZ, aNi);
                gemm_half(g_h1T[par],               256, b0, sA, sW, cx, by, tid, aR, aZ, aNh);
                float gr[4], gz[4], gi[4], gh[4];
                unpk(aR, gr); unpk(aZ, gz); unpk(aNi, gi); unpk(aNh, gh);
                float4 hv = *(const float4*)&g_h1T[par][hoff];
                float hold[4] = {hv.x, hv.y, hv.z, hv.w};
                float res[4];
                #pragma unroll
                for (int i = 0; i < 4; ++i) {
                    float r = sigf(gr[i] + bR);
                    float z = sigf(gz[i] + bZ);
                    float n = tanhf(gi[i] + bNi + r * (gh[i] + bNh));
                    res[i] = (1.f - z) * n + z * hold[i];
                }
                *(float4*)&g_h1T[par ^ 1][hoff] = make_float4(res[0], res[1], res[2], res[3]);
            }
        } else {
            if (p >= 1) {
                // layer2: h2(p) = GRU(h1(p), h2(p-1))
                ull iR[2] = {0, 0}, iZ[2] = {0, 0}, iN[2] = {0, 0};
                ull hR[2] = {0, 0}, hZ[2] = {0, 0}, hN[2] = {0, 0};
                gemm_half(g_h1T[par], 0,   b0, sA, sW, cx, by, tid, iR, iZ, iN);
                gemm_half(g_h2T[par], 256, b0, sA, sW, cx, by, tid, hR, hZ, hN);
                float ir[4], iz[4], in_[4], hr[4], hz[4], hn[4];
                unpk(iR, ir); unpk(iZ, iz); unpk(iN, in_);
                unpk(hR, hr); unpk(hZ, hz); unpk(hN, hn);
                float4 hv = *(const float4*)&g_h2T[par][hoff];
                float hold[4] = {hv.x, hv.y, hv.z, hv.w};
                float res[4];
                #pragma unroll
                for (int i = 0; i < 4; ++i) {
                    float r = sigf(ir[i] + hr[i] + bR);
                    float z = sigf(iz[i] + hz[i] + bZ);
                    float n = tanhf(in_[i] + bNi + r * (hn[i] + bNh));
                    res[i] = (1.f - z) * n + z * hold[i];
                }
                if (p == SEQ) {
                    // write final h2 directly to out[b][j]
                    int bb = b0 + by * 4;
                    out[(bb + 0) * 256 + j] = res[0];
                    out[(bb + 1) * 256 + j] = res[1];
                    out[(bb + 2) * 256 + j] = res[2];
                    out[(bb + 3) * 256 + j] = res[3];
                } else {
                    *(float4*)&g_h2T[par ^ 1][hoff] = make_float4(res[0], res[1], res[2], res[3]);
                }
            }
        }
        if (p < SEQ) grid_sync();
    }
}

// ---------------- host launch ----------------
extern "C" void kernel_launch(void* const* d_in, const int* in_sizes, int n_in,
                              void* d_out, int out_size) {
    (void)in_sizes; (void)n_in; (void)out_size;
    const float* x     = (const float*)d_in[0];
    const float* h1    = (const float*)d_in[1];
    const float* h2    = (const float*)d_in[2];
    const float* w_ih1 = (const float*)d_in[3];
    const float* w_hh1 = (const float*)d_in[4];
    const float* b_ih1 = (const float*)d_in[5];
    const float* b_hh1 = (const float*)d_in[6];
    const float* w_ih2 = (const float*)d_in[7];
    const float* w_hh2 = (const float*)d_in[8];
    const float* b_ih2 = (const float*)d_in[9];
    const float* b_hh2 = (const float*)d_in[10];
    float* out = (float*)d_out;

    const int SMEM_BYTES = 512 * 48 * 8 + 2 * 32 * 64 * 4;  // 212992
    cudaFuncSetAttribute(k_main, cudaFuncAttributeMaxDynamicSharedMemorySize, SMEM_BYTES);

    k_init<<<256, 256>>>(h1, h2);
    k_scales<<<4, 512>>>(w_ih1, w_hh1, w_ih2, w_hh2);
    k_pack<<<512, 256>>>(w_ih1, w_hh1, w_ih2, w_hh2);
    dim3 tg(8, 8, SEQ);
    k_transx<<<tg, 256>>>(x);
    k_main<<<128, 256, SMEM_BYTES>>>(b_ih1, b_hh1, b_ih2, b_hh2, out);
}

// round 8
// speedup vs baseline: 3.3161x; 1.7995x over previous
#include <cuda_runtime.h>
#include <cuda_bf16.h>
#include <math.h>
#include <stdint.h>

#define SEQ 512

typedef unsigned int u32;
typedef unsigned long long u64;

// ---------------- device globals (no cudaMalloc allowed) ----------------
// quantized integer-valued weights (bf16-exact), layout gW[k*768 + c], c = gate*256 + j
__device__ float gW1x[256 * 768];
__device__ float gW1h[256 * 768];
__device__ float gW2i[256 * 768];
__device__ float gW2h[256 * 768];

// activations as bf16 hi/lo planes, [b][k] row-major
__device__ __nv_bfloat16 g_xhi[(size_t)SEQ * 65536];
__device__ __nv_bfloat16 g_xlo[(size_t)SEQ * 65536];
__device__ __nv_bfloat16 g_h1hi[2][65536];
__device__ __nv_bfloat16 g_h1lo[2][65536];
__device__ __nv_bfloat16 g_h2hi[2][65536];
__device__ __nv_bfloat16 g_h2lo[2][65536];
// full-precision hidden state (for the z*h_old path)
__device__ float g_h1f[2][65536];
__device__ float g_h2f[2][65536];

__device__ float g_scale[4];
__device__ unsigned g_bar;

// ---------------- helpers ----------------
__device__ __forceinline__ u32 smem_u32(const void* p) {
    u32 a;
    asm("{ .reg .u64 t; cvta.to.shared.u64 t, %1; cvt.u32.u64 %0, t; }" : "=r"(a) : "l"(p));
    return a;
}

#define LDMATRIX4(r, a) \
    asm volatile("ldmatrix.sync.aligned.m8n8.x4.shared.b16 {%0,%1,%2,%3}, [%4];" \
        : "=r"((r)[0]), "=r"((r)[1]), "=r"((r)[2]), "=r"((r)[3]) : "r"(a))

#define MMA16816(d, a, b0, b1) \
    asm volatile("mma.sync.aligned.m16n8k16.row.col.f32.bf16.bf16.f32 " \
        "{%0,%1,%2,%3}, {%4,%5,%6,%7}, {%8,%9}, {%0,%1,%2,%3};" \
        : "+f"((d)[0]), "+f"((d)[1]), "+f"((d)[2]), "+f"((d)[3]) \
        : "r"((a)[0]), "r"((a)[1]), "r"((a)[2]), "r"((a)[3]), "r"(b0), "r"(b1))

#define LDS64(r0, r1, a) \
    asm volatile("ld.shared.v2.b32 {%0,%1}, [%2];" : "=r"(r0), "=r"(r1) : "r"(a))

#define STS64F(a, x, y) \
    asm volatile("st.shared.v2.f32 [%0], {%1,%2};" :: "r"(a), "f"(x), "f"(y) : "memory")

#define STS128(a, v) \
    asm volatile("st.shared.v4.b32 [%0], {%1,%2,%3,%4};" \
        :: "r"(a), "r"((v).x), "r"((v).y), "r"((v).z), "r"((v).w) : "memory")

__device__ __forceinline__ u32 pkbf(float x, float y) {
    __nv_bfloat162 t = __floats2bfloat162_rn(x, y);
    return *(u32*)&t;
}

__device__ __forceinline__ float sigf(float x) { return 1.f / (1.f + expf(-x)); }

// ---------------- setup kernels ----------------
__global__ void k_init(const float* __restrict__ h1, const float* __restrict__ h2) {
    int i = blockIdx.x * blockDim.x + threadIdx.x;
    if (i == 0) g_bar = 0u;
    if (i < 65536) {
        float v1 = h1[i], v2 = h2[i];
        g_h1f[0][i] = v1;
        g_h2f[1][i] = v2;
        __nv_bfloat16 a = __float2bfloat16(v1);
        g_h1hi[0][i] = a;
        g_h1lo[0][i] = __float2bfloat16(v1 - __bfloat162float(a));
        __nv_bfloat16 b = __float2bfloat16(v2);
        g_h2hi[1][i] = b;
        g_h2lo[1][i] = __float2bfloat16(v2 - __bfloat162float(b));
    }
}

__global__ void k_scales(const float* __restrict__ w0, const float* __restrict__ w1,
                         const float* __restrict__ w2, const float* __restrict__ w3) {
    const float* w = (blockIdx.x == 0) ? w0 : (blockIdx.x == 1) ? w1
                   : (blockIdx.x == 2) ? w2 : w3;
    const int n = 768 * 256;
    float m = 0.f;
    for (int i = threadIdx.x; i < n; i += blockDim.x) m = fmaxf(m, fabsf(w[i]));
    __shared__ float sm[512];
    sm[threadIdx.x] = m;
    __syncthreads();
    for (int s = blockDim.x >> 1; s > 0; s >>= 1) {
        if (threadIdx.x < s) sm[threadIdx.x] = fmaxf(sm[threadIdx.x], sm[threadIdx.x + s]);
        __syncthreads();
    }
    if (threadIdx.x == 0) g_scale[blockIdx.x] = sm[0] / 127.0f;
}

// gW[k*768 + c] = rint(W[c*256 + k] / s)   (c = gate*256 + j; |v| <= 127, bf16-exact)
__global__ void k_pack(const float* __restrict__ wih1, const float* __restrict__ whh1,
                       const float* __restrict__ wih2, const float* __restrict__ whh2) {
    const float s0 = g_scale[0], s1 = g_scale[1], s2 = g_scale[2], s3 = g_scale[3];
    const int N = 256 * 768;
    for (int i = blockIdx.x * blockDim.x + threadIdx.x; i < N;
         i += gridDim.x * blockDim.x) {
        int k = i / 768, c = i - k * 768;
        int off = c * 256 + k;
        gW1x[i] = rintf(wih1[off] / s0);
        gW1h[i] = rintf(whh1[off] / s1);
        gW2i[i] = rintf(wih2[off] / s2);
        gW2h[i] = rintf(whh2[off] / s3);
    }
}

// x -> bf16 hi/lo planes
__global__ void k_convx(const float* __restrict__ x) {
    size_t i = ((size_t)blockIdx.x * blockDim.x + threadIdx.x) * 4;
    if (i >= (size_t)SEQ * 65536) return;
    float4 v = *(const float4*)(x + i);
    float vv[4] = {v.x, v.y, v.z, v.w};
    __nv_bfloat16 hi[4], lo[4];
    #pragma unroll
    for (int r = 0; r < 4; ++r) {
        hi[r] = __float2bfloat16(vv[r]);
        lo[r] = __float2bfloat16(vv[r] - __bfloat162float(hi[r]));
    }
    *(uint2*)(g_xhi + i) = *(uint2*)hi;
    *(uint2*)(g_xlo + i) = *(uint2*)lo;
}

// ---------------- grid barrier (G = 128) ----------------
__device__ __forceinline__ void grid_sync() {
    __syncthreads();
    if (threadIdx.x == 0) {
        __threadfence();
        unsigned t = atomicAdd(&g_bar, 1u) + 1u;
        unsigned target = ((t + 127u) / 128u) * 128u;
        while (*(volatile unsigned*)&g_bar < target) { }
        __threadfence();
    }
    __syncthreads();
}

// ---------------- main persistent kernel ----------------
// 128 CTAs x 128 threads. CTA 0..63 = layer1, 64..127 = layer2.
// CTA tile: M=64 batch rows x N=48 (16 j x 3 gates, n = j*3+gate). 4 M-tiles x 16 N-tiles.
// Warp grid 2Mx2N: warp tile 32 x 24 (2 m-frags x 3 n-tiles).
// SMEM: bias @0 (256B), B frag stream @1024 (48KB), A planes @50176 (4 x 33792B).
//       epilogue gi/gh buffers alias the A region.
#define S_BF   1024
#define S_A    50176
#define A_STR  528
#define A_PL   33792
#define GI_O   50176
#define GH_O   62976
#define SMEM_BYTES 185344

__global__ void __launch_bounds__(128) k_main(
    const float* __restrict__ b_ih1, const float* __restrict__ b_hh1,
    const float* __restrict__ b_ih2, const float* __restrict__ b_hh2,
    float* __restrict__ out)
{
    extern __shared__ char smem[];
    const u32 sbase = smem_u32(smem);
    float* sBias = (float*)smem;
    const float* gi = (const float*)(smem + GI_O);
    const float* gh = (const float*)(smem + GH_O);

    const int tid = threadIdx.x;
    const int ln = tid & 31, w = tid >> 5;
    const int bid = blockIdx.x;
    const bool isL2 = bid >= 64;
    const int tb = isL2 ? bid - 64 : bid;
    const int b0 = (tb >> 4) * 64;
    const int j0 = (tb & 15) * 16;
    const int mbase = (w & 1) * 32;     // warp M offset
    const int ntb = (w >> 1) * 3;       // warp N-tile base (tiles of 8)

    // ---- one-time: B fragment stream (2 sources x 16 ksteps x 6 tiles x 32 lanes x 8B)
    {
        const float* Ws = (w >> 1) ? (isL2 ? gW2h : gW1h) : (isL2 ? gW2i : gW1x);
        const int s = w >> 1;
        const int n = (ln >> 2);        // n within tile = groupID
        const int tg = ln & 3;
        for (int ks = (w & 1) * 8; ks < (w & 1) * 8 + 8; ++ks) {
            #pragma unroll
            for (int gt = 0; gt < 6; ++gt) {
                int ng = gt * 8 + n;
                int j = j0 + ng / 3;
                int gate = ng - 3 * (ng / 3);
                int c = gate * 256 + j;
                int k0 = ks * 16 + tg * 2;
                u32 f0 = pkbf(Ws[(size_t)k0 * 768 + c], Ws[(size_t)(k0 + 1) * 768 + c]);
                u32 f1 = pkbf(Ws[(size_t)(k0 + 8) * 768 + c], Ws[(size_t)(k0 + 9) * 768 + c]);
                u32 ad = sbase + S_BF + (u32)((((s * 16 + ks) * 6 + gt) * 32 + ln) * 8);
                asm volatile("st.shared.v2.b32 [%0], {%1,%2};" :: "r"(ad), "r"(f0), "r"(f1) : "memory");
            }
        }
    }
    if (tid < 16) {
        int j = j0 + tid;
        const float* bi = isL2 ? b_ih2 : b_ih1;
        const float* bh = isL2 ? b_hh2 : b_hh1;
        sBias[tid * 4 + 0] = bi[j] + bh[j];
        sBias[tid * 4 + 1] = bi[j + 256] + bh[j + 256];
        sBias[tid * 4 + 2] = bi[j + 512];
        sBias[tid * 4 + 3] = bh[j + 512];
    }
    const float s_i = isL2 ? g_scale[2] : g_scale[0];
    const float s_h = isL2 ? g_scale[3] : g_scale[1];
    __syncthreads();

    for (int p = 0; p <= SEQ; ++p) {
        const int par = p & 1;
        const bool active = isL2 ? (p >= 1) : (p < SEQ);
        if (active) {
            const __nv_bfloat16* planes[4];
            const float* hf;
            if (!isL2) {
                planes[0] = g_xhi + (size_t)p * 65536;
                planes[1] = g_xlo + (size_t)p * 65536;
                planes[2] = g_h1hi[par]; planes[3] = g_h1lo[par];
                hf = g_h1f[par];
            } else {
                planes[0] = g_h1hi[par]; planes[1] = g_h1lo[par];
                planes[2] = g_h2hi[par]; planes[3] = g_h2lo[par];
                hf = g_h2f[par];
            }

            // ---- stage A: 4 planes x 64 rows x 256 k (bf16), padded stride 528B
            {
                const int row = tid >> 1, half = tid & 1;
                #pragma unroll
                for (int pair = 0; pair < 2; ++pair) {
                    uint4 P[32];
                    #pragma unroll
                    for (int q = 0; q < 2; ++q) {
                        const uint4* src = (const uint4*)(planes[pair * 2 + q]
                            + (size_t)(b0 + row) * 256 + half * 128);
                        #pragma unroll
                        for (int i = 0; i < 16; ++i) P[q * 16 + i] = __ldcg(src + i);
                    }
                    #pragma unroll
                    for (int q = 0; q < 2; ++q) {
                        u32 ad = sbase + S_A + (u32)(pair * 2 + q) * A_PL
                               + (u32)row * A_STR + (u32)half * 256u;
                        #pragma unroll
                        for (int i = 0; i < 16; ++i) STS128(ad + (u32)i * 16u, P[q * 16 + i]);
                    }
                }
            }
            __syncthreads();

            // ---- MMA mainloop
            float acci[2][3][4] = {}, acch[2][3][4] = {};
            #pragma unroll
            for (int s = 0; s < 2; ++s) {
                #pragma unroll 4
                for (int ks = 0; ks < 16; ++ks) {
                    u32 a[2][2][4];
                    #pragma unroll
                    for (int mf = 0; mf < 2; ++mf)
                        #pragma unroll
                        for (int q = 0; q < 2; ++q) {
                            u32 ad = sbase + S_A + (u32)(s * 2 + q) * A_PL
                                   + (u32)(mbase + mf * 16 + (ln & 15)) * A_STR
                                   + (u32)(ks * 32 + (ln >> 4) * 16);
                            LDMATRIX4(a[mf][q], ad);
                        }
                    #pragma unroll
                    for (int nt = 0; nt < 3; ++nt) {
                        u32 f0, f1;
                        u32 bad = sbase + S_BF
                                + (u32)((((s * 16 + ks) * 6 + ntb + nt) * 32 + ln) * 8);
                        LDS64(f0, f1, bad);
                        #pragma unroll
                        for (int mf = 0; mf < 2; ++mf)
                            #pragma unroll
                            for (int q = 0; q < 2; ++q) {
                                if (s == 0) { MMA16816(acci[mf][nt], a[mf][q], f0, f1); }
                                else        { MMA16816(acch[mf][nt], a[mf][q], f0, f1); }
                            }
                    }
                }
            }
            __syncthreads();   // all warps done with A region before aliasing as gi/gh

            // ---- scatter fragments to gi/gh buffers (stride 50 floats)
            #pragma unroll
            for (int s = 0; s < 2; ++s) {
                u32 base = sbase + (s ? GH_O : GI_O);
                #pragma unroll
                for (int mf = 0; mf < 2; ++mf)
                    #pragma unroll
                    for (int nt = 0; nt < 3; ++nt) {
                        int row = mbase + mf * 16 + (ln >> 2);
                        int col = (ntb + nt) * 8 + (ln & 3) * 2;
                        float* acc = s ? acch[mf][nt] : acci[mf][nt];
                        STS64F(base + (u32)(row * 50 + col) * 4, acc[0], acc[1]);
                        STS64F(base + (u32)((row + 8) * 50 + col) * 4, acc[2], acc[3]);
                    }
            }
            __syncthreads();

            // ---- GRU gate epilogue: thread -> (b = b0 + tid/2, 8 j's)
            {
                const int bl = tid >> 1, jh = (tid & 1) * 8;
                const int b = b0 + bl;
                float hold[8];
                *(float4*)&hold[0] = __ldcg((const float4*)(hf + (size_t)b * 256 + j0 + jh));
                *(float4*)&hold[4] = __ldcg((const float4*)(hf + (size_t)b * 256 + j0 + jh + 4));
                float res[8];
                #pragma unroll
                for (int jj = 0; jj < 8; ++jj) {
                    int jl = jh + jj;
                    float gir = gi[bl * 50 + jl * 3 + 0];
                    float giz = gi[bl * 50 + jl * 3 + 1];
                    float gin = gi[bl * 50 + jl * 3 + 2];
                    float ghr = gh[bl * 50 + jl * 3 + 0];
                    float ghz = gh[bl * 50 + jl * 3 + 1];
                    float ghn = gh[bl * 50 + jl * 3 + 2];
                    float r = sigf(s_i * gir + s_h * ghr + sBias[jl * 4 + 0]);
                    float z = sigf(s_i * giz + s_h * ghz + sBias[jl * 4 + 1]);
                    float n = tanhf(s_i * gin + sBias[jl * 4 + 2]
                                    + r * (s_h * ghn + sBias[jl * 4 + 3]));
                    res[jj] = (1.f - z) * n + z * hold[jj];
                }
                if (isL2 && p == SEQ) {
                    float4* o4 = (float4*)(out + (size_t)b * 256 + j0 + jh);
                    o4[0] = ((float4*)res)[0];
                    o4[1] = ((float4*)res)[1];
                } else {
                    float* hfN;
                    __nv_bfloat16 *hhiN, *hloN;
                    if (!isL2) { hfN = g_h1f[par ^ 1]; hhiN = g_h1hi[par ^ 1]; hloN = g_h1lo[par ^ 1]; }
                    else       { hfN = g_h2f[par ^ 1]; hhiN = g_h2hi[par ^ 1]; hloN = g_h2lo[par ^ 1]; }
                    float4* o4 = (float4*)(hfN + (size_t)b * 256 + j0 + jh);
                    o4[0] = ((float4*)res)[0];
                    o4[1] = ((float4*)res)[1];
                    __nv_bfloat16 hi[8], lo[8];
                    #pragma unroll
                    for (int jj = 0; jj < 8; ++jj) {
                        hi[jj] = __float2bfloat16(res[jj]);
                        lo[jj] = __float2bfloat16(res[jj] - __bfloat162float(hi[jj]));
                    }
                    *(uint4*)(hhiN + (size_t)b * 256 + j0 + jh) = *(uint4*)hi;
                    *(uint4*)(hloN + (size_t)b * 256 + j0 + jh) = *(uint4*)lo;
                }
            }
        }
        if (p < SEQ) grid_sync();
    }
}

// ---------------- host launch ----------------
extern "C" void kernel_launch(void* const* d_in, const int* in_sizes, int n_in,
                              void* d_out, int out_size) {
    (void)in_sizes; (void)n_in; (void)out_size;
    const float* x     = (const float*)d_in[0];
    const float* h1    = (const float*)d_in[1];
    const float* h2    = (const float*)d_in[2];
    const float* w_ih1 = (const float*)d_in[3];
    const float* w_hh1 = (const float*)d_in[4];
    const float* b_ih1 = (const float*)d_in[5];
    const float* b_hh1 = (const float*)d_in[6];
    const float* w_ih2 = (const float*)d_in[7];
    const float* w_hh2 = (const float*)d_in[8];
    const float* b_ih2 = (const float*)d_in[9];
    const float* b_hh2 = (const float*)d_in[10];
    float* out = (float*)d_out;

    cudaFuncSetAttribute(k_main, cudaFuncAttributeMaxDynamicSharedMemorySize, SMEM_BYTES);

    k_init<<<256, 256>>>(h1, h2);
    k_scales<<<4, 512>>>(w_ih1, w_hh1, w_ih2, w_hh2);
    k_pack<<<512, 256>>>(w_ih1, w_hh1, w_ih2, w_hh2);
    k_convx<<<32768, 256>>>(x);
    k_main<<<128, 128, SMEM_BYTES>>>(b_ih1, b_hh1, b_ih2, b_hh2, out);
}

// round 9
// speedup vs baseline: 5.0139x; 1.5120x over previous
#include <cuda_runtime.h>
#include <cuda_bf16.h>
#include <math.h>
#include <stdint.h>

#define SEQ 512

typedef unsigned int u32;
typedef unsigned long long u64;

// ---------------- device globals (no cudaMalloc allowed) ----------------
// quantized integer-valued weights (bf16-exact), layout gW[k*768 + c], c = gate*256 + j
__device__ float gW1x[256 * 768];
__device__ float gW1h[256 * 768];
__device__ float gW2i[256 * 768];
__device__ float gW2h[256 * 768];

// activations as bf16 hi/lo planes, [b][k] row-major
__device__ __nv_bfloat16 g_xhi[(size_t)SEQ * 65536];
__device__ __nv_bfloat16 g_xlo[(size_t)SEQ * 65536];
__device__ __nv_bfloat16 g_h1hi[2][65536];
__device__ __nv_bfloat16 g_h1lo[2][65536];
__device__ __nv_bfloat16 g_h2hi[2][65536];
__device__ __nv_bfloat16 g_h2lo[2][65536];
// full-precision hidden state (for the z*h_old path)
__device__ float g_h1f[2][65536];
__device__ float g_h2f[2][65536];

__device__ float g_scale[4];
__device__ unsigned g_bar;

// ---------------- helpers ----------------
__device__ __forceinline__ u32 smem_u32(const void* p) {
    u32 a;
    asm("{ .reg .u64 t; cvta.to.shared.u64 t, %1; cvt.u32.u64 %0, t; }" : "=r"(a) : "l"(p));
    return a;
}

#define LDMATRIX4(r, a) \
    asm volatile("ldmatrix.sync.aligned.m8n8.x4.shared.b16 {%0,%1,%2,%3}, [%4];" \
        : "=r"((r)[0]), "=r"((r)[1]), "=r"((r)[2]), "=r"((r)[3]) : "r"(a))

#define MMA16816(d, a, b0, b1) \
    asm volatile("mma.sync.aligned.m16n8k16.row.col.f32.bf16.bf16.f32 " \
        "{%0,%1,%2,%3}, {%4,%5,%6,%7}, {%8,%9}, {%0,%1,%2,%3};" \
        : "+f"((d)[0]), "+f"((d)[1]), "+f"((d)[2]), "+f"((d)[3]) \
        : "r"((a)[0]), "r"((a)[1]), "r"((a)[2]), "r"((a)[3]), "r"(b0), "r"(b1))

#define LDS64(r0, r1, a) \
    asm volatile("ld.shared.v2.b32 {%0,%1}, [%2];" : "=r"(r0), "=r"(r1) : "r"(a))

#define CPA16(dst, src) \
    asm volatile("cp.async.cg.shared.global [%0], [%1], 16;" :: "r"(dst), "l"(src) : "memory")
#define CPA_COMMIT() asm volatile("cp.async.commit_group;" ::: "memory")
#define CPA_WAIT(N)  asm volatile("cp.async.wait_group %0;" :: "n"(N) : "memory")

__device__ __forceinline__ u32 pkbf(float x, float y) {
    __nv_bfloat162 t = __floats2bfloat162_rn(x, y);
    return *(u32*)&t;
}

__device__ __forceinline__ float sigf(float x) { return 1.f / (1.f + expf(-x)); }

// ---------------- setup kernels ----------------
__global__ void k_init(const float* __restrict__ h1, const float* __restrict__ h2) {
    int i = blockIdx.x * blockDim.x + threadIdx.x;
    if (i == 0) g_bar = 0u;
    if (i < 65536) {
        float v1 = h1[i], v2 = h2[i];
        g_h1f[0][i] = v1;
        g_h2f[1][i] = v2;
        __nv_bfloat16 a = __float2bfloat16(v1);
        g_h1hi[0][i] = a;
        g_h1lo[0][i] = __float2bfloat16(v1 - __bfloat162float(a));
        __nv_bfloat16 b = __float2bfloat16(v2);
        g_h2hi[1][i] = b;
        g_h2lo[1][i] = __float2bfloat16(v2 - __bfloat162float(b));
    }
}

__global__ void k_scales(const float* __restrict__ w0, const float* __restrict__ w1,
                         const float* __restrict__ w2, const float* __restrict__ w3) {
    const float* w = (blockIdx.x == 0) ? w0 : (blockIdx.x == 1) ? w1
                   : (blockIdx.x == 2) ? w2 : w3;
    const int n = 768 * 256;
    float m = 0.f;
    for (int i = threadIdx.x; i < n; i += blockDim.x) m = fmaxf(m, fabsf(w[i]));
    __shared__ float sm[512];
    sm[threadIdx.x] = m;
    __syncthreads();
    for (int s = blockDim.x >> 1; s > 0; s >>= 1) {
        if (threadIdx.x < s) sm[threadIdx.x] = fmaxf(sm[threadIdx.x], sm[threadIdx.x + s]);
        __syncthreads();
    }
    if (threadIdx.x == 0) g_scale[blockIdx.x] = sm[0] / 127.0f;
}

// gW[k*768 + c] = rint(W[c*256 + k] / s)   (c = gate*256 + j; |v| <= 127, bf16-exact)
__global__ void k_pack(const float* __restrict__ wih1, const float* __restrict__ whh1,
                       const float* __restrict__ wih2, const float* __restrict__ whh2) {
    const float s0 = g_scale[0], s1 = g_scale[1], s2 = g_scale[2], s3 = g_scale[3];
    const int N = 256 * 768;
    for (int i = blockIdx.x * blockDim.x + threadIdx.x; i < N;
         i += gridDim.x * blockDim.x) {
        int k = i / 768, c = i - k * 768;
        int off = c * 256 + k;
        gW1x[i] = rintf(wih1[off] / s0);
        gW1h[i] = rintf(whh1[off] / s1);
        gW2i[i] = rintf(wih2[off] / s2);
        gW2h[i] = rintf(whh2[off] / s3);
    }
}

// x -> bf16 hi/lo planes
__global__ void k_convx(const float* __restrict__ x) {
    size_t i = ((size_t)blockIdx.x * blockDim.x + threadIdx.x) * 4;
    if (i >= (size_t)SEQ * 65536) return;
    float4 v = *(const float4*)(x + i);
    float vv[4] = {v.x, v.y, v.z, v.w};
    __nv_bfloat16 hi[4], lo[4];
    #pragma unroll
    for (int r = 0; r < 4; ++r) {
        hi[r] = __float2bfloat16(vv[r]);
        lo[r] = __float2bfloat16(vv[r] - __bfloat162float(hi[r]));
    }
    *(uint2*)(g_xhi + i) = *(uint2*)hi;
    *(uint2*)(g_xlo + i) = *(uint2*)lo;
}

// ---------------- grid barrier (G = 128) ----------------
__device__ __forceinline__ void grid_sync() {
    __syncthreads();
    if (threadIdx.x == 0) {
        __threadfence();
        unsigned t = atomicAdd(&g_bar, 1u) + 1u;
        unsigned target = ((t + 127u) / 128u) * 128u;
        while (*(volatile unsigned*)&g_bar < target) { }
        __threadfence();
    }
    __syncthreads();
}

// ---------------- main persistent kernel ----------------
// 128 CTAs x 256 threads. CTA 0..63 = layer1, 64..127 = layer2.
// CTA tile: M=64 batch rows x N=48 (GATE-MAJOR: n = gate*16 + jlocal).
// Warp grid 4M x 2N: wm = w&3 (16 rows), wn = w>>2 (j-half of 8).
// Each warp: 3 n-tiles = gates r/z/n of its 8 j's -> register epilogue.
// SMEM: bias @0, B frag stream @1024 (48KB), A planes @50176 (4 x 33792B).
#define S_BF   1024
#define S_A    50176
#define A_STR  528
#define A_PL   33792
#define SMEM_BYTES 185344

__global__ void __launch_bounds__(256) k_main(
    const float* __restrict__ b_ih1, const float* __restrict__ b_hh1,
    const float* __restrict__ b_ih2, const float* __restrict__ b_hh2,
    float* __restrict__ out)
{
    extern __shared__ char smem[];
    const u32 sbase = smem_u32(smem);
    float* sBias = (float*)smem;

    const int tid = threadIdx.x;
    const int ln = tid & 31, w = tid >> 5;
    const int wm = w & 3, wn = w >> 2;
    const int bid = blockIdx.x;
    const bool isL2 = bid >= 64;
    const int tb = isL2 ? bid - 64 : bid;
    const int b0 = (tb >> 4) * 64;
    const int j0 = (tb & 15) * 16;

    // ---- one-time: B fragment stream (2 src x 16 ksteps x 6 tiles x 32 lanes x 8B)
    // tile tt: gate = tt>>1, j-half = (tt&1)*8
    {
        const int sB = w & 1;
        const float* Ws = sB ? (isL2 ? gW2h : gW1h) : (isL2 ? gW2i : gW1x);
        const int n = ln >> 2, kp = ln & 3;
        for (int ks = (w >> 1) * 4; ks < (w >> 1) * 4 + 4; ++ks) {
            #pragma unroll
            for (int tt = 0; tt < 6; ++tt) {
                int j = j0 + (tt & 1) * 8 + n;
                int c = (tt >> 1) * 256 + j;
                int k0 = ks * 16 + kp * 2;
                u32 f0 = pkbf(Ws[(size_t)k0 * 768 + c], Ws[(size_t)(k0 + 1) * 768 + c]);
                u32 f1 = pkbf(Ws[(size_t)(k0 + 8) * 768 + c], Ws[(size_t)(k0 + 9) * 768 + c]);
                u32 ad = sbase + S_BF + (u32)((((sB * 16 + ks) * 6 + tt) * 32 + ln) * 8);
                asm volatile("st.shared.v2.b32 [%0], {%1,%2};" :: "r"(ad), "r"(f0), "r"(f1) : "memory");
            }
        }
    }
    if (tid < 16) {
        int j = j0 + tid;
        const float* bi = isL2 ? b_ih2 : b_ih1;
        const float* bh = isL2 ? b_hh2 : b_hh1;
        sBias[tid * 4 + 0] = bi[j] + bh[j];
        sBias[tid * 4 + 1] = bi[j + 256] + bh[j + 256];
        sBias[tid * 4 + 2] = bi[j + 512];
        sBias[tid * 4 + 3] = bh[j + 512];
    }
    const float s_i = isL2 ? g_scale[2] : g_scale[0];
    const float s_h = isL2 ? g_scale[3] : g_scale[1];
    __syncthreads();

    // per-lane constants
    const int jb = j0 + wn * 8 + (ln & 3) * 2;        // global j of col pair
    const int b_r = b0 + wm * 16 + (ln >> 2);         // global batch row (frag row r)
    const int jl = wn * 8 + (ln & 3) * 2;             // local j
    float bR[2], bZ[2], bNi[2], bNh[2];
    #pragma unroll
    for (int cc = 0; cc < 2; ++cc) {
        bR[cc]  = sBias[(jl + cc) * 4 + 0];
        bZ[cc]  = sBias[(jl + cc) * 4 + 1];
        bNi[cc] = sBias[(jl + cc) * 4 + 2];
        bNh[cc] = sBias[(jl + cc) * 4 + 3];
    }
    const u32 a_base = sbase + S_A + (u32)(wm * 16 + (ln & 15)) * A_STR + (u32)((ln >> 4) * 16);
    const int cp_row = tid >> 2;             // 0..63
    const int cp_seg = (tid & 3) * 64;       // byte segment within 256B half-row

    for (int p = 0; p <= SEQ; ++p) {
        const int par = p & 1;
        const bool active = isL2 ? (p >= 1) : (p < SEQ);
        if (active) {
            const __nv_bfloat16* planes[4];
            const float* hf;
            if (!isL2) {
                planes[0] = g_xhi + (size_t)p * 65536;
                planes[1] = g_xlo + (size_t)p * 65536;
                planes[2] = g_h1hi[par]; planes[3] = g_h1lo[par];
                hf = g_h1f[par];
            } else {
                planes[0] = g_h1hi[par]; planes[1] = g_h1lo[par];
                planes[2] = g_h2hi[par]; planes[3] = g_h2lo[par];
                hf = g_h2f[par];
            }

            // ---- issue all 4 A-chunks (source x k-half) as cp.async commit groups
            #pragma unroll
            for (int c = 0; c < 4; ++c) {
                const int s = c >> 1, kh = c & 1;
                #pragma unroll
                for (int pq = 0; pq < 2; ++pq) {
                    const char* srcb = (const char*)planes[s * 2 + pq]
                        + (size_t)(b0 + cp_row) * 512 + kh * 256 + cp_seg;
                    u32 dst = sbase + S_A + (u32)(s * 2 + pq) * A_PL
                            + (u32)cp_row * A_STR + (u32)(kh * 256 + cp_seg);
                    #pragma unroll
                    for (int i = 0; i < 4; ++i) CPA16(dst + i * 16, srcb + i * 16);
                }
                CPA_COMMIT();
            }

            // ---- prefetch h_old (latency hidden under MMA)
            float2 h01 = __ldcg((const float2*)(hf + (size_t)b_r * 256 + jb));
            float2 h89 = __ldcg((const float2*)(hf + (size_t)(b_r + 8) * 256 + jb));

            float acci[3][4] = {}, acch[3][4] = {};

            // ---- MMA chunks, each overlapping remaining cp.async traffic
            #define DO_CHUNK(C, WAITN) do { \
                CPA_WAIT(WAITN); \
                __syncthreads(); \
                const int s = (C) >> 1, kh = (C) & 1; \
                _Pragma("unroll") \
                for (int k8 = 0; k8 < 8; ++k8) { \
                    const int ks = kh * 8 + k8; \
                    u32 a[2][4]; \
                    _Pragma("unroll") \
                    for (int q = 0; q < 2; ++q) \
                        LDMATRIX4(a[q], a_base + (u32)(s * 2 + q) * A_PL + (u32)(ks * 32)); \
                    _Pragma("unroll") \
                    for (int g = 0; g < 3; ++g) { \
                        u32 f0, f1; \
                        u32 bad = sbase + S_BF \
                                + (u32)((((s * 16 + ks) * 6 + g * 2 + wn) * 32 + ln) * 8); \
                        LDS64(f0, f1, bad); \
                        if (s == 0) { \
                            MMA16816(acci[g], a[0], f0, f1); \
                            MMA16816(acci[g], a[1], f0, f1); \
                        } else { \
                            MMA16816(acch[g], a[0], f0, f1); \
                            MMA16816(acch[g], a[1], f0, f1); \
                        } \
                    } \
                } \
            } while (0)

            DO_CHUNK(0, 3);
            DO_CHUNK(1, 2);
            DO_CHUNK(2, 1);
            DO_CHUNK(3, 0);
            #undef DO_CHUNK

            // ---- register GRU epilogue: lane owns (rows b_r, b_r+8) x (cols jb, jb+1)
            float res[2][2];
            #pragma unroll
            for (int rh = 0; rh < 2; ++rh) {
                #pragma unroll
                for (int cc = 0; cc < 2; ++cc) {
                    const int k = rh * 2 + cc;
                    float r = sigf(fmaf(s_i, acci[0][k], fmaf(s_h, acch[0][k], bR[cc])));
                    float z = sigf(fmaf(s_i, acci[1][k], fmaf(s_h, acch[1][k], bZ[cc])));
                    float n = tanhf(fmaf(s_i, acci[2][k], bNi[cc])
                                    + r * fmaf(s_h, acch[2][k], bNh[cc]));
                    float hold = rh ? (cc ? h89.y : h89.x) : (cc ? h01.y : h01.x);
                    res[rh][cc] = (1.f - z) * n + z * hold;
                }
            }

            if (isL2 && p == SEQ) {
                *(float2*)(out + (size_t)b_r * 256 + jb) = make_float2(res[0][0], res[0][1]);
                *(float2*)(out + (size_t)(b_r + 8) * 256 + jb) = make_float2(res[1][0], res[1][1]);
            } else {
                float* hfN;
                __nv_bfloat16 *hhiN, *hloN;
                if (!isL2) { hfN = g_h1f[par ^ 1]; hhiN = g_h1hi[par ^ 1]; hloN = g_h1lo[par ^ 1]; }
                else       { hfN = g_h2f[par ^ 1]; hhiN = g_h2hi[par ^ 1]; hloN = g_h2lo[par ^ 1]; }
                #pragma unroll
                for (int rh = 0; rh < 2; ++rh) {
                    const size_t off = (size_t)(b_r + rh * 8) * 256 + jb;
                    *(float2*)(hfN + off) = make_float2(res[rh][0], res[rh][1]);
                    __nv_bfloat16 hi0 = __float2bfloat16(res[rh][0]);
                    __nv_bfloat16 hi1 = __float2bfloat16(res[rh][1]);
                    float lo0 = res[rh][0] - __bfloat162float(hi0);
                    float lo1 = res[rh][1] - __bfloat162float(hi1);
                    __nv_bfloat162 hp; hp.x = hi0; hp.y = hi1;
                    *(u32*)(hhiN + off) = *(u32*)&hp;
                    *(u32*)(hloN + off) = pkbf(lo0, lo1);
                }
            }
        }
        if (p < SEQ) grid_sync();
    }
}

// ---------------- host launch ----------------
extern "C" void kernel_launch(void* const* d_in, const int* in_sizes, int n_in,
                              void* d_out, int out_size) {
    (void)in_sizes; (void)n_in; (void)out_size;
    const float* x     = (const float*)d_in[0];
    const float* h1    = (const float*)d_in[1];
    const float* h2    = (const float*)d_in[2];
    const float* w_ih1 = (const float*)d_in[3];
    const float* w_hh1 = (const float*)d_in[4];
    const float* b_ih1 = (const float*)d_in[5];
    const float* b_hh1 = (const float*)d_in[6];
    const float* w_ih2 = (const float*)d_in[7];
    const float* w_hh2 = (const float*)d_in[8];
    const float* b_ih2 = (const float*)d_in[9];
    const float* b_hh2 = (const float*)d_in[10];
    float* out = (float*)d_out;

    cudaFuncSetAttribute(k_main, cudaFuncAttributeMaxDynamicSharedMemorySize, SMEM_BYTES);

    k_init<<<256, 256>>>(h1, h2);
    k_scales<<<4, 512>>>(w_ih1, w_hh1, w_ih2, w_hh2);
    k_pack<<<512, 256>>>(w_ih1, w_hh1, w_ih2, w_hh2);
    k_convx<<<32768, 256>>>(x);
    k_main<<<128, 256, SMEM_BYTES>>>(b_ih1, b_hh1, b_ih2, b_hh2, out);
}